// round 9
// baseline (speedup 1.0000x reference)
#include <cuda_runtime.h>
#include <cuda_bf16.h>

// Problem constants (fixed by the reference)
#define BB      2
#define XX      200
#define YY      200
#define ZZ      16      // == HEIGHT, h = 1
#define CC      17
#define EMPTY_LABEL 16
#define CHOOSE  4000

#define TPB 256
#define COLS_PER_BLK 16
#define BLKS_PER_B (CHOOSE / COLS_PER_BLK)    // 250
#define GRID2 (BB * BLKS_PER_B)               // 500
#define GRID1 ((BB * CHOOSE + TPB - 1) / TPB) // 32

#define COL_BYTES (ZZ * CC * 4)               // 1088
#define LAB_BYTES (ZZ * 4)                    // 64
#define TX_PER_WARP (2 * COL_BYTES + 2 * LAB_BYTES)  // 2304

// Persistent device scratch (allocation-free).
// g_cnt / g_loss start zero and are re-zeroed by the last K2 block every call.
// g_ticket is MONOTONIC (never reset).
__device__ int                 g_cnt[BB * ZZ];
__device__ float               g_loss[BB];
__device__ unsigned long long  g_ticket;

// ---- TMA bulk copy + mbarrier helpers --------------------------------------
__device__ __forceinline__ void bulk_cp(unsigned dst_smem, const void* src,
                                        unsigned bytes, unsigned mbar) {
    asm volatile(
        "cp.async.bulk.shared::cta.global.mbarrier::complete_tx::bytes "
        "[%0], [%1], %2, [%3];"
        :: "r"(dst_smem), "l"(src), "r"(bytes), "r"(mbar) : "memory");
}
__device__ __forceinline__ void mbar_init(unsigned mbar, unsigned count) {
    asm volatile("mbarrier.init.shared.b64 [%0], %1;" :: "r"(mbar), "r"(count) : "memory");
}
__device__ __forceinline__ void mbar_expect_tx(unsigned mbar, unsigned tx) {
    asm volatile("mbarrier.arrive.expect_tx.shared.b64 _, [%0], %1;"
                 :: "r"(mbar), "r"(tx) : "memory");
}
__device__ __forceinline__ void mbar_wait0(unsigned mbar) {
    asm volatile(
        "{\n\t.reg .pred P;\n\t"
        "WL_%=:\n\t"
        "mbarrier.try_wait.parity.shared.b64 P, [%0], 0, 0x989680;\n\t"
        "@P bra WD_%=;\n\t"
        "bra WL_%=;\n\t"
        "WD_%=:\n\t}"
        :: "r"(mbar) : "memory");
}
__device__ __forceinline__ void mbar_inval(unsigned mbar) {
    asm volatile("mbarrier.inval.shared.b64 [%0];" :: "r"(mbar) : "memory");
}

// ---------------------------------------------------------------------------
// K1: per-(b,z) valid-label counts. 8000 columns, one thread each.
__global__ void __launch_bounds__(TPB)
k1_counts(const int* __restrict__ labels, const int* __restrict__ sel) {
    __shared__ int s_cnt[BB * ZZ];
    const int tid = threadIdx.x;
    const int t = blockIdx.x * TPB + tid;
    if (tid < BB * ZZ) s_cnt[tid] = 0;
    __syncthreads();

    if (t < BB * CHOOSE) {
        const int b = t / CHOOSE;
        const int2 xy = __ldg((const int2*)sel + t);
        const int col = (b * XX + xy.x) * YY + xy.y;
        const int4* __restrict__ lp = (const int4*)(labels + (long long)col * ZZ);
        int4 l[4];
        #pragma unroll
        for (int q = 0; q < 4; q++) l[q] = __ldg(lp + q);

        const int lane = tid & 31;
        #pragma unroll
        for (int q = 0; q < 4; q++) {
            unsigned m0 = __ballot_sync(0xffffffffu, l[q].x != EMPTY_LABEL);
            unsigned m1 = __ballot_sync(0xffffffffu, l[q].y != EMPTY_LABEL);
            unsigned m2 = __ballot_sync(0xffffffffu, l[q].z != EMPTY_LABEL);
            unsigned m3 = __ballot_sync(0xffffffffu, l[q].w != EMPTY_LABEL);
            if (lane == 0) {
                atomicAdd(&s_cnt[b * ZZ + q * 4 + 0], __popc(m0));
                atomicAdd(&s_cnt[b * ZZ + q * 4 + 1], __popc(m1));
                atomicAdd(&s_cnt[b * ZZ + q * 4 + 2], __popc(m2));
                atomicAdd(&s_cnt[b * ZZ + q * 4 + 3], __popc(m3));
            }
        }
    }
    __syncthreads();
    if (tid < BB * ZZ && s_cnt[tid]) atomicAdd(&g_cnt[tid], s_cnt[tid]);
}

// ---------------------------------------------------------------------------
// K2: warp-autonomous; staging via 4 TMA bulk copies per warp (one per
// column / label row), completion via per-warp smem mbarrier. Weight math
// overlaps the TMA flight.
__global__ void __launch_bounds__(TPB)
k2_loss(const float* __restrict__ preds,
        const int*   __restrict__ labels,
        const int*   __restrict__ sel,
        float*       __restrict__ out) {
    const int bid = blockIdx.x;
    const int tid = threadIdx.x;
    const int b  = bid / BLKS_PER_B;
    const int cb = bid % BLKS_PER_B;
    const int w    = tid >> 5;
    const int lane = tid & 31;

    __shared__ __align__(128) float s_pred[COLS_PER_BLK * ZZ * CC];  // 17408B
    __shared__ __align__(128) int   s_lab [COLS_PER_BLK * ZZ];       // 1024B
    __shared__ __align__(16)  unsigned long long s_mbar[TPB / 32];   // 8 mbarriers
    __shared__ float s_wsum[TPB / 32];

    const unsigned mbar = (unsigned)__cvta_generic_to_shared(&s_mbar[w]);

    // ---- sel for this warp's 2 columns (lanes 0,1), broadcast --------------
    int colv = 0;
    if (lane < 2) {
        int2 xy = __ldg((const int2*)sel + b * CHOOSE + cb * COLS_PER_BLK + 2 * w + lane);
        colv = (b * XX + xy.x) * YY + xy.y;
    }
    const int colA = __shfl_sync(0xffffffffu, colv, 0);
    const int colB = __shfl_sync(0xffffffffu, colv, 1);

    // ---- lane 0: init mbarrier, expect 2304B, fire 4 bulk copies ------------
    if (lane == 0) {
        mbar_init(mbar, 1);
        // init->use ordering: same thread, program order + async-proxy fence
        asm volatile("fence.proxy.async.shared::cta;" ::: "memory");
        mbar_expect_tx(mbar, TX_PER_WARP);
        unsigned dA = (unsigned)__cvta_generic_to_shared(s_pred + (2 * w)     * (ZZ * CC));
        unsigned dB = (unsigned)__cvta_generic_to_shared(s_pred + (2 * w + 1) * (ZZ * CC));
        unsigned lA = (unsigned)__cvta_generic_to_shared(s_lab + (2 * w)     * ZZ);
        unsigned lB = (unsigned)__cvta_generic_to_shared(s_lab + (2 * w + 1) * ZZ);
        bulk_cp(dA, preds  + (long long)colA * (ZZ * CC), COL_BYTES, mbar);
        bulk_cp(dB, preds  + (long long)colB * (ZZ * CC), COL_BYTES, mbar);
        bulk_cp(lA, labels + (long long)colA * ZZ,        LAB_BYTES, mbar);
        bulk_cp(lB, labels + (long long)colB * ZZ,        LAB_BYTES, mbar);
    }

    // ---- weights in registers (overlaps the TMA flight) --------------------
    const int z = lane & 15;
    const int cz = g_cnt[b * ZZ + z];            // L2 hit (written by K1)
    int maxc = cz;
    #pragma unroll
    for (int o = 1; o < 16; o <<= 1)
        maxc = max(maxc, __shfl_xor_sync(0xffffffffu, maxc, o));
    const float maxcf = fmaxf((float)maxc, 1.0f);
    const float LOG_RATIO = -1.0986122886681098f;   // ln(1/3)
    const float wz = (cz > 0) ? 3.0f * __expf(((float)cz / maxcf) * LOG_RATIO) : 0.0f;

    // ---- wait for this warp's TMA completion --------------------------------
    __syncwarp();
    mbar_wait0(mbar);
    __syncwarp();

    // ---- softmax + smooth-L1: lane -> (col = 2w + (lane>>4), z = lane&15) ---
    const int lcl = lane >> 4;
    const int lab = s_lab[(2 * w + lcl) * ZZ + z];
    float val = 0.0f;
    if (lab != EMPTY_LABEL) {
        const float* __restrict__ p = s_pred + (2 * w + lcl) * (ZZ * CC) + z * CC;
        float s = 0.0f;
        #pragma unroll
        for (int c = 0; c < CC; c++) s += __expf(p[c]);   // conflict-free LDS
        const float plab = __fdividef(__expf(p[lab]), s);
        const float ll = __logf(plab + 0.001f);
        const float wl = wz * ll;
        const float ax = fabsf(wl);
        val = (ax < 1.0f) ? 0.5f * wl * wl : (ax - 0.5f);
    }

    // ---- warp reduce -> smem; single block sync; one global atomic ----------
    #pragma unroll
    for (int off = 16; off > 0; off >>= 1)
        val += __shfl_down_sync(0xffffffffu, val, off);
    if (lane == 0) {
        s_wsum[w] = val;
        mbar_inval(mbar);
    }
    __syncthreads();

    if (tid == 0) {
        float v = 0.0f;
        #pragma unroll
        for (int i = 0; i < TPB / 32; i++) v += s_wsum[i];
        atomicAdd(&g_loss[b], v);
        __threadfence();

        // ticket: last block finalizes + resets accumulators
        unsigned long long old = atomicAdd(&g_ticket, 1ULL);
        if ((old % GRID2) == (GRID2 - 1)) {
            __threadfence();  // acquire all g_loss updates
            int n0 = 0, n1 = 0;
            #pragma unroll
            for (int z2 = 0; z2 < ZZ; z2++) { n0 += g_cnt[z2]; n1 += g_cnt[ZZ + z2]; }
            float r0 = g_loss[0] / fmaxf((float)n0, 1.0f);
            float r1 = g_loss[1] / fmaxf((float)n1, 1.0f);
            out[0] = 0.5f * (r0 + r1);
            // reset for next call (graph replay / re-validation)
            #pragma unroll
            for (int z2 = 0; z2 < BB * ZZ; z2++) g_cnt[z2] = 0;
            g_loss[0] = 0.0f;
            g_loss[1] = 0.0f;
        }
    }
}

extern "C" void kernel_launch(void* const* d_in, const int* in_sizes, int n_in,
                              void* d_out, int out_size) {
    const float* preds  = nullptr;
    const int*   labels = nullptr;
    const int*   sel    = nullptr;
    for (int i = 0; i < n_in; i++) {
        if (in_sizes[i] == BB * XX * YY * ZZ * CC)      preds  = (const float*)d_in[i];
        else if (in_sizes[i] == BB * XX * YY * ZZ)      labels = (const int*)d_in[i];
        else if (in_sizes[i] == BB * CHOOSE * 2)        sel    = (const int*)d_in[i];
    }
    k1_counts<<<GRID1, TPB>>>(labels, sel);
    k2_loss<<<GRID2, TPB>>>(preds, labels, sel, (float*)d_out);
}

// round 10
// speedup vs baseline: 1.2019x; 1.2019x over previous
#include <cuda_runtime.h>
#include <cuda_bf16.h>

// Problem constants (fixed by the reference)
#define BB      2
#define XX      200
#define YY      200
#define ZZ      16      // == HEIGHT, h = 1
#define CC      17
#define EMPTY_LABEL 16
#define CHOOSE  4000

#define TPB 256
#define COLS_PER_BLK 16
#define BLKS_PER_B (CHOOSE / COLS_PER_BLK)    // 250
#define GRID2 (BB * BLKS_PER_B)               // 500
#define GRID1 ((BB * CHOOSE + TPB - 1) / TPB) // 32

// Persistent device scratch (allocation-free).
// g_cnt / g_loss start zero (static init) and are re-zeroed by K3 every call,
// so each call/replay starts from zeros. No monotonic counters needed anymore.
__device__ int   g_cnt[BB * ZZ];
__device__ float g_loss[BB];

__device__ __forceinline__ void cp16(unsigned smem_addr, const void* gptr) {
    asm volatile("cp.async.cg.shared.global [%0], [%1], 16;"
                 :: "r"(smem_addr), "l"(gptr));
}

// ---------------------------------------------------------------------------
// K1: per-(b,z) valid-label counts. 8000 columns, one thread each.
__global__ void __launch_bounds__(TPB)
k1_counts(const int* __restrict__ labels, const int* __restrict__ sel) {
    __shared__ int s_cnt[BB * ZZ];
    const int tid = threadIdx.x;
    const int t = blockIdx.x * TPB + tid;
    if (tid < BB * ZZ) s_cnt[tid] = 0;
    __syncthreads();

    if (t < BB * CHOOSE) {
        const int b = t / CHOOSE;
        const int2 xy = __ldg((const int2*)sel + t);
        const int col = (b * XX + xy.x) * YY + xy.y;
        const int4* __restrict__ lp = (const int4*)(labels + (long long)col * ZZ);
        int4 l[4];
        #pragma unroll
        for (int q = 0; q < 4; q++) l[q] = __ldg(lp + q);

        const int lane = tid & 31;
        #pragma unroll
        for (int q = 0; q < 4; q++) {
            unsigned m0 = __ballot_sync(0xffffffffu, l[q].x != EMPTY_LABEL);
            unsigned m1 = __ballot_sync(0xffffffffu, l[q].y != EMPTY_LABEL);
            unsigned m2 = __ballot_sync(0xffffffffu, l[q].z != EMPTY_LABEL);
            unsigned m3 = __ballot_sync(0xffffffffu, l[q].w != EMPTY_LABEL);
            if (lane == 0) {
                atomicAdd(&s_cnt[b * ZZ + q * 4 + 0], __popc(m0));
                atomicAdd(&s_cnt[b * ZZ + q * 4 + 1], __popc(m1));
                atomicAdd(&s_cnt[b * ZZ + q * 4 + 2], __popc(m2));
                atomicAdd(&s_cnt[b * ZZ + q * 4 + 3], __popc(m3));
            }
        }
    }
    __syncthreads();
    if (tid < BB * ZZ && s_cnt[tid]) atomicAdd(&g_cnt[tid], s_cnt[tid]);
}

// ---------------------------------------------------------------------------
// K2: warp-autonomous, cp.async staging; ends with ONE fire-and-forget RED
// per block. No ticket, no blocking atomic, no end-of-kernel convoy.
__global__ void __launch_bounds__(TPB)
k2_loss(const float* __restrict__ preds,
        const int*   __restrict__ labels,
        const int*   __restrict__ sel) {
    const int bid = blockIdx.x;
    const int tid = threadIdx.x;
    const int b  = bid / BLKS_PER_B;
    const int cb = bid % BLKS_PER_B;
    const int w    = tid >> 5;
    const int lane = tid & 31;

    __shared__ float s_pred[COLS_PER_BLK * ZZ * CC];   // 17408B
    __shared__ int   s_lab [COLS_PER_BLK * ZZ];        // 1KB
    __shared__ float s_wsum[TPB / 32];

    // ---- sel for this warp's 2 columns (lanes 0,1), broadcast --------------
    int colv = 0;
    if (lane < 2) {
        int2 xy = __ldg((const int2*)sel + b * CHOOSE + cb * COLS_PER_BLK + 2 * w + lane);
        colv = (b * XX + xy.x) * YY + xy.y;
    }
    const int colA = __shfl_sync(0xffffffffu, colv, 0);
    const int colB = __shfl_sync(0xffffffffu, colv, 1);

    // ---- fire ALL staging as cp.async (no register buffering) --------------
    {
        const float4* __restrict__ srcA = (const float4*)preds + (long long)colA * 68;
        const float4* __restrict__ srcB = (const float4*)preds + (long long)colB * 68;
        unsigned dstA = (unsigned)__cvta_generic_to_shared(s_pred + (2 * w)     * (ZZ * CC));
        unsigned dstB = (unsigned)__cvta_generic_to_shared(s_pred + (2 * w + 1) * (ZZ * CC));
        cp16(dstA + lane * 16,        srcA + lane);
        cp16(dstB + lane * 16,        srcB + lane);
        cp16(dstA + (lane + 32) * 16, srcA + lane + 32);
        cp16(dstB + (lane + 32) * 16, srcB + lane + 32);
        if (lane < 4) {
            cp16(dstA + (lane + 64) * 16, srcA + lane + 64);
            cp16(dstB + (lane + 64) * 16, srcB + lane + 64);
        }
        if (lane < 8) {
            int c = (lane < 4) ? colA : colB;
            unsigned dl = (unsigned)__cvta_generic_to_shared(
                              s_lab + (2 * w + (lane >> 2)) * ZZ) + (lane & 3) * 16;
            cp16(dl, (const int4*)(labels + (long long)c * ZZ) + (lane & 3));
        }
        asm volatile("cp.async.commit_group;");
    }

    // ---- weights in registers (overlaps the async fetch) -------------------
    const int z = lane & 15;
    const int cz = g_cnt[b * ZZ + z];            // L2 hit (written by K1)
    int maxc = cz;
    #pragma unroll
    for (int o = 1; o < 16; o <<= 1)
        maxc = max(maxc, __shfl_xor_sync(0xffffffffu, maxc, o));
    const float maxcf = fmaxf((float)maxc, 1.0f);
    const float LOG_RATIO = -1.0986122886681098f;   // ln(1/3)
    const float wz = (cz > 0) ? 3.0f * __expf(((float)cz / maxcf) * LOG_RATIO) : 0.0f;

    // ---- wait for this warp's copies; consume from smem --------------------
    asm volatile("cp.async.wait_group 0;");
    __syncwarp();

    const int lcl = lane >> 4;
    const int lab = s_lab[(2 * w + lcl) * ZZ + z];
    float val = 0.0f;
    if (lab != EMPTY_LABEL) {
        const float* __restrict__ p = s_pred + (2 * w + lcl) * (ZZ * CC) + z * CC;
        float s = 0.0f;
        #pragma unroll
        for (int c = 0; c < CC; c++) s += __expf(p[c]);   // conflict-free LDS
        const float plab = __fdividef(__expf(p[lab]), s);
        const float ll = __logf(plab + 0.001f);
        const float wl = wz * ll;
        const float ax = fabsf(wl);
        val = (ax < 1.0f) ? 0.5f * wl * wl : (ax - 0.5f);
    }

    // ---- warp reduce -> smem; one fire-and-forget RED per block ------------
    #pragma unroll
    for (int off = 16; off > 0; off >>= 1)
        val += __shfl_down_sync(0xffffffffu, val, off);
    if (lane == 0) s_wsum[w] = val;
    __syncthreads();

    if (tid == 0) {
        float v = 0.0f;
        #pragma unroll
        for (int i = 0; i < TPB / 32; i++) v += s_wsum[i];
        atomicAdd(&g_loss[b], v);   // RED: no return value, non-blocking
    }
}

// ---------------------------------------------------------------------------
// K3: finalize + reset (one warp; all loads parallel, 2 RTTs total).
__global__ void k3_final(float* __restrict__ out) {
    const int lane = threadIdx.x;
    int c = g_cnt[lane];                     // lanes 0-15: batch0, 16-31: batch1
    float l = (lane < BB) ? g_loss[lane] : 0.0f;

    int n = c;
    #pragma unroll
    for (int o = 1; o < 16; o <<= 1)
        n += __shfl_xor_sync(0xffffffffu, n, o);   // sums within 16-lane halves

    const int   n0 = __shfl_sync(0xffffffffu, n, 0);
    const int   n1 = __shfl_sync(0xffffffffu, n, 16);
    const float l0 = __shfl_sync(0xffffffffu, l, 0);
    const float l1 = __shfl_sync(0xffffffffu, l, 1);

    if (lane == 0) {
        float r0 = l0 / fmaxf((float)n0, 1.0f);
        float r1 = l1 / fmaxf((float)n1, 1.0f);
        out[0] = 0.5f * (r0 + r1);
    }
    // reset for next call (graph replay / re-validation)
    g_cnt[lane] = 0;
    if (lane < BB) g_loss[lane] = 0.0f;
}

extern "C" void kernel_launch(void* const* d_in, const int* in_sizes, int n_in,
                              void* d_out, int out_size) {
    const float* preds  = nullptr;
    const int*   labels = nullptr;
    const int*   sel    = nullptr;
    for (int i = 0; i < n_in; i++) {
        if (in_sizes[i] == BB * XX * YY * ZZ * CC)      preds  = (const float*)d_in[i];
        else if (in_sizes[i] == BB * XX * YY * ZZ)      labels = (const int*)d_in[i];
        else if (in_sizes[i] == BB * CHOOSE * 2)        sel    = (const int*)d_in[i];
    }
    k1_counts<<<GRID1, TPB>>>(labels, sel);
    k2_loss<<<GRID2, TPB>>>(preds, labels, sel);
    k3_final<<<1, 32>>>((float*)d_out);
}